// round 6
// baseline (speedup 1.0000x reference)
#include <cuda_runtime.h>
#include <cuda_bf16.h>

#define N_ASSETS   128
#define BATCH      2048
#define N_ITERS    300
#define ROUNDS     16        // fallback multisection rounds (4^16 == 2^32)
#define LR         0.02f
#define EPS        1e-8f
#define CMAX       1.0f
#define BR_LO     (-2.5f)
#define BR_HI      (2.5f)

typedef unsigned long long ull;

__device__ __forceinline__ ull pack2(float x, float y) {
    ull r; asm("mov.b64 %0, {%1, %2};" : "=l"(r) : "f"(x), "f"(y)); return r;
}
__device__ __forceinline__ ull ffma2(ull a, ull b, ull c) {
    ull r; asm("fma.rn.f32x2 %0, %1, %2, %3;" : "=l"(r) : "l"(a), "l"(b), "l"(c)); return r;
}
__device__ __forceinline__ ull fadd2(ull a, ull b) {
    ull r; asm("add.rn.f32x2 %0, %1, %2;" : "=l"(r) : "l"(a), "l"(b)); return r;
}
__device__ __forceinline__ float2 unpack2(ull v) {
    float2 f; asm("mov.b64 {%0, %1}, %2;" : "=f"(f.x), "=f"(f.y) : "l"(v)); return f;
}

__global__ void __launch_bounds__(256, 2)
markowitz_kernel(const float* __restrict__ rets,
                 const float* __restrict__ cov,
                 const float* __restrict__ gamma,
                 const float* __restrict__ alpha,
                 float* __restrict__ out)
{
    __shared__ __align__(16) float w_sh[N_ASSETS];
    __shared__ float parts_sh[N_ASSETS];          // h=1 partials; reused for v
    __shared__ __align__(16) float wsum[8][4];    // per-warp (pa, sAw, sw, pw)
    __shared__ int flag_sh;

    const int b    = blockIdx.x;
    const int t    = threadIdx.x;
    const int i    = t & 127;      // asset row
    const int h    = t >> 7;       // half of the row's dot product
    const int wid  = t >> 5;
    const int lane = t & 31;

    // ---- A = gamma * covmat into registers as 32 packed f32x2 pairs ----
    ull ap[32];
    {
        const float g = gamma[b];
        const float* Ab = cov + (size_t)b * N_ASSETS * N_ASSETS
                              + (size_t)i * N_ASSETS + h * 64;
        #pragma unroll
        for (int k = 0; k < 16; ++k) {
            float4 c4 = *reinterpret_cast<const float4*>(Ab + 4 * k);
            ap[2 * k + 0] = pack2(g * c4.x, g * c4.y);
            ap[2 * k + 1] = pack2(g * c4.z, g * c4.w);
        }
    }

    // ---- per-asset state (h=0 threads own asset i == t) ----
    float w_reg = 1.0f / (float)N_ASSETS;
    float r_i = 0.f, aab = 0.f, sum_r = 0.f;
    if (h == 0) {
        r_i = rets[(size_t)b * N_ASSETS + i];
        aab = fabsf(alpha[b]);
    }
    if (t < N_ASSETS) w_sh[t] = 1.0f / (float)N_ASSETS;
    if (t == 0) flag_sh = 0;

    // one-time block reduction of sum(rets)
    {
        float s = (h == 0) ? r_i : 0.f;
        #pragma unroll
        for (int off = 16; off; off >>= 1)
            s += __shfl_xor_sync(0xffffffffu, s, off);
        if (lane == 0) wsum[wid][0] = s;
    }
    __syncthreads();
    if (h == 0)
        sum_r = wsum[0][0] + wsum[1][0] + wsum[2][0] + wsum[3][0];
    __syncthreads();   // wsum gets reused inside the loop

    const double2* w2 = reinterpret_cast<const double2*>(w_sh) + h * 16;

    for (int it = 0; it < N_ITERS; ++it) {
        // ---- half matvec via packed dual-fp32 FMA (32 FFMA2 / thread) ----
        ull acc0 = 0ull, acc1 = 0ull;
        #pragma unroll
        for (int k = 0; k < 8; ++k) {
            double2 wd = w2[2 * k];
            double2 we = w2[2 * k + 1];
            acc0 = ffma2(ap[4 * k + 0], __double_as_longlong(wd.x), acc0);
            acc1 = ffma2(ap[4 * k + 1], __double_as_longlong(wd.y), acc1);
            acc0 = ffma2(ap[4 * k + 2], __double_as_longlong(we.x), acc0);
            acc1 = ffma2(ap[4 * k + 3], __double_as_longlong(we.y), acc1);
        }
        float2 sv2 = unpack2(fadd2(acc0, acc1));
        const float my_part = sv2.x + sv2.y;
        if (h) parts_sh[i] = my_part;

        // ---- local contributions + parallel per-warp 4-tuple reduction ----
        const float wv  = (h == 0) ? w_reg : w_sh[i];
        float red0 = wv * my_part;               // -> pa  (w'Aw)
        float red1 = my_part;                    // -> sAw (sum Aw)
        float red2 = (h == 0) ? wv : 0.f;        // -> sw
        float red3 = (h == 0) ? wv * wv : 0.f;   // -> pw
        #pragma unroll
        for (int off = 16; off; off >>= 1) {
            red0 += __shfl_xor_sync(0xffffffffu, red0, off);
            red1 += __shfl_xor_sync(0xffffffffu, red1, off);
            red2 += __shfl_xor_sync(0xffffffffu, red2, off);
            red3 += __shfl_xor_sync(0xffffffffu, red3, off);
        }
        if (lane == 0)
            *reinterpret_cast<float4*>(wsum[wid]) = make_float4(red0, red1, red2, red3);
        __syncthreads();

        // ---- distributed update: each h=0 thread updates its own asset ----
        if (h == 0) {
            float pa = 0.f, sAw = 0.f, sw = 0.f, pw = 0.f;
            #pragma unroll
            for (int wdx = 0; wdx < 8; ++wdx) {
                float4 v4 = *reinterpret_cast<const float4*>(wsum[wdx]);
                pa  += v4.x;
                sAw += v4.y;
                sw  += v4.z;
                pw  += v4.w;
            }
            const float inv_risk = rsqrtf(pa + EPS);
            const float an       = aab * rsqrtf(pw + EPS);
            const float Aw_i     = my_part + parts_sh[i];
            const float v_i = fmaf(LR, r_i - Aw_i * inv_risk - an * w_reg, w_reg);

            // closed-form tau (exact when no element clips)
            const float sv  = sw + LR * (sum_r - sAw * inv_risk - an * sw);
            const float tau = (sv - 1.0f) * (1.0f / (float)N_ASSETS);

            const bool ok = __all_sync(0xffffffffu, fabsf(v_i - tau) <= CMAX);
            w_reg = fminf(fmaxf(v_i - tau, -CMAX), CMAX);
            w_sh[i] = w_reg;
            parts_sh[i] = v_i;                    // stash v for rare fallback
            if (!ok && lane == 0) flag_sh = 1;
        }
        __syncthreads();

        if (flag_sh) {
            // ---- rare slow path: warp 0 multisection over v ----
            if (wid == 0) {
                float vq[4];
                #pragma unroll
                for (int q = 0; q < 4; ++q) vq[q] = parts_sh[lane + 32 * q];
                float lo = BR_LO, hi = BR_HI;
                #pragma unroll 1
                for (int r = 0; r < ROUNDS; ++r) {
                    const float qw = 0.25f * (hi - lo);
                    const float m1 = lo + qw;
                    const float m2 = lo + 2.0f * qw;
                    const float m3 = lo + 3.0f * qw;
                    float s1 = 0.f, s2 = 0.f, s3 = 0.f;
                    #pragma unroll
                    for (int q = 0; q < 4; ++q) {
                        const float v = vq[q];
                        s1 += fminf(fmaxf(v - m1, -CMAX), CMAX);
                        s2 += fminf(fmaxf(v - m2, -CMAX), CMAX);
                        s3 += fminf(fmaxf(v - m3, -CMAX), CMAX);
                    }
                    #pragma unroll
                    for (int off = 16; off; off >>= 1) {
                        s1 += __shfl_xor_sync(0xffffffffu, s1, off);
                        s2 += __shfl_xor_sync(0xffffffffu, s2, off);
                        s3 += __shfl_xor_sync(0xffffffffu, s3, off);
                    }
                    float kf = 0.f;
                    if (s1 > 1.0f) kf += 1.0f;
                    if (s2 > 1.0f) kf += 1.0f;
                    if (s3 > 1.0f) kf += 1.0f;
                    lo = fmaf(kf, qw, lo);
                    hi = lo + qw;
                }
                const float tau2 = 0.5f * (lo + hi);
                #pragma unroll
                for (int q = 0; q < 4; ++q)
                    w_sh[lane + 32 * q] =
                        fminf(fmaxf(vq[q] - tau2, -CMAX), CMAX);
            }
            __syncthreads();
            if (h == 0) w_reg = w_sh[i];
            if (t == 0) flag_sh = 0;
            __syncthreads();
        }
    }

    if (t < N_ASSETS) out[(size_t)b * N_ASSETS + t] = w_reg;
}

extern "C" void kernel_launch(void* const* d_in, const int* in_sizes, int n_in,
                              void* d_out, int out_size)
{
    const float* rets  = (const float*)d_in[0];   // [2048,128]
    const float* cov   = (const float*)d_in[1];   // [2048,128,128]
    const float* gamma = (const float*)d_in[2];   // [2048]
    const float* alpha = (const float*)d_in[3];   // [2048]
    float* out = (float*)d_out;                   // [2048,128]

    markowitz_kernel<<<BATCH, 256>>>(rets, cov, gamma, alpha, out);
}

// round 7
// speedup vs baseline: 1.3846x; 1.3846x over previous
#include <cuda_runtime.h>
#include <cuda_bf16.h>

#define N_ASSETS   128
#define BATCH      2048
#define N_ITERS    300
#define ROUNDS     16        // fallback multisection rounds (4^16 == 2^32)
#define LR         0.02f
#define EPS        1e-8f
#define CMAX       1.0f
#define BR_LO     (-2.5f)
#define BR_HI      (2.5f)

typedef unsigned long long ull;

__device__ __forceinline__ ull pack2(float x, float y) {
    ull r; asm("mov.b64 %0, {%1, %2};" : "=l"(r) : "f"(x), "f"(y)); return r;
}
__device__ __forceinline__ ull ffma2(ull a, ull b, ull c) {
    ull r; asm("fma.rn.f32x2 %0, %1, %2, %3;" : "=l"(r) : "l"(a), "l"(b), "l"(c)); return r;
}
__device__ __forceinline__ ull fadd2(ull a, ull b) {
    ull r; asm("add.rn.f32x2 %0, %1, %2;" : "=l"(r) : "l"(a), "l"(b)); return r;
}
__device__ __forceinline__ float2 unpack2(ull v) {
    float2 f; asm("mov.b64 {%0, %1}, %2;" : "=f"(f.x), "=f"(f.y) : "l"(v)); return f;
}

#define BAR_ARRIVE(id) asm volatile("bar.arrive %0, 256;" :: "n"(id) : "memory")
#define BAR_SYNCN(id)  asm volatile("bar.sync %0, 256;"   :: "n"(id) : "memory")

__global__ void __launch_bounds__(256, 2)
markowitz_kernel(const float* __restrict__ rets,
                 const float* __restrict__ cov,
                 const float* __restrict__ gamma,
                 const float* __restrict__ alpha,
                 float* __restrict__ out)
{
    __shared__ __align__(16) float w_sh[N_ASSETS];
    __shared__ float parts_sh[2 * N_ASSETS];

    const int b    = blockIdx.x;
    const int t    = threadIdx.x;
    const int i    = t & 127;      // asset row
    const int h    = t >> 7;       // half of the row's dot product
    const int wid  = t >> 5;
    const int lane = t & 31;

    // ---- A = gamma * covmat into registers as 32 packed f32x2 pairs ----
    ull ap[32];
    {
        const float g = gamma[b];
        const float* Ab = cov + (size_t)b * N_ASSETS * N_ASSETS
                              + (size_t)i * N_ASSETS + h * 64;
        #pragma unroll
        for (int k = 0; k < 16; ++k) {
            float4 c4 = *reinterpret_cast<const float4*>(Ab + 4 * k);
            ap[2 * k + 0] = pack2(g * c4.x, g * c4.y);
            ap[2 * k + 1] = pack2(g * c4.z, g * c4.w);
        }
    }

    const int wsel = b & 7;
    float rq0 = 0.f, rq1 = 0.f, rq2 = 0.f, rq3 = 0.f;
    float aab = 0.f, sum_r = 0.f;
    if (wid == wsel) {
        const float* rb = rets + (size_t)b * N_ASSETS;
        rq0 = rb[lane +  0];
        rq1 = rb[lane + 32];
        rq2 = rb[lane + 64];
        rq3 = rb[lane + 96];
        aab = fabsf(alpha[b]);
        sum_r = ((rq0 + rq1) + (rq2 + rq3));
        #pragma unroll
        for (int off = 16; off; off >>= 1)
            sum_r += __shfl_xor_sync(0xffffffffu, sum_r, off);
    }

    if (t < N_ASSETS) w_sh[t] = 1.0f / (float)N_ASSETS;
    __syncthreads();

    // double2 = 16 bytes = 4 floats; this half's 64 floats start at index h*16
    const double2* w2 = reinterpret_cast<const double2*>(w_sh) + h * 16;

    for (int it = 0; it < N_ITERS; ++it) {
        // ---- half matvec via packed dual-fp32 FMA (32 FFMA2 / thread) ----
        ull acc0 = 0ull, acc1 = 0ull;
        #pragma unroll
        for (int k = 0; k < 8; ++k) {
            double2 wd = w2[2 * k];
            double2 we = w2[2 * k + 1];
            acc0 = ffma2(ap[4 * k + 0], __double_as_longlong(wd.x), acc0);
            acc1 = ffma2(ap[4 * k + 1], __double_as_longlong(wd.y), acc1);
            acc0 = ffma2(ap[4 * k + 2], __double_as_longlong(we.x), acc0);
            acc1 = ffma2(ap[4 * k + 3], __double_as_longlong(we.y), acc1);
        }
        float2 s = unpack2(fadd2(acc0, acc1));
        parts_sh[h * N_ASSETS + i] = s.x + s.y;

        if (wid != wsel) {
            BAR_ARRIVE(1);          // my partial is posted
            BAR_SYNCN(2);           // wait for updated w
        } else {
            BAR_SYNCN(1);           // wait for all partials

            float wq[4], Aq[4], vq[4];
            float pa = 0.f, pw = 0.f, sAw = 0.f;
            #pragma unroll
            for (int q = 0; q < 4; ++q) {
                const int idx = lane + 32 * q;
                wq[q] = w_sh[idx];
                Aq[q] = parts_sh[idx] + parts_sh[N_ASSETS + idx];
                pa  = fmaf(wq[q], Aq[q], pa);
                pw  = fmaf(wq[q], wq[q], pw);
                sAw += Aq[q];
            }
            #pragma unroll
            for (int off = 16; off; off >>= 1) {
                pa  += __shfl_xor_sync(0xffffffffu, pa,  off);
                pw  += __shfl_xor_sync(0xffffffffu, pw,  off);
                sAw += __shfl_xor_sync(0xffffffffu, sAw, off);
            }
            const float inv_risk = rsqrtf(pa + EPS);
            const float an       = aab * rsqrtf(pw + EPS);

            vq[0] = fmaf(LR, rq0 - Aq[0] * inv_risk - an * wq[0], wq[0]);
            vq[1] = fmaf(LR, rq1 - Aq[1] * inv_risk - an * wq[1], wq[1]);
            vq[2] = fmaf(LR, rq2 - Aq[2] * inv_risk - an * wq[2], wq[2]);
            vq[3] = fmaf(LR, rq3 - Aq[3] * inv_risk - an * wq[3], wq[3]);

            // closed-form tau using sum(w)==1 (simplex invariant):
            // tau = LR*(sum_r - sAw*inv_risk - an) / 128
            float tau = LR * (sum_r - sAw * inv_risk - an)
                           * (1.0f / (float)N_ASSETS);

            float mx = 0.f;
            #pragma unroll
            for (int q = 0; q < 4; ++q)
                mx = fmaxf(mx, fabsf(vq[q] - tau));
            const bool ok = __all_sync(0xffffffffu, mx <= CMAX);

            if (!ok) {
                // rare fallback: 3-probe multisection on constant bracket
                float lo = BR_LO, hi = BR_HI;
                #pragma unroll 1
                for (int r = 0; r < ROUNDS; ++r) {
                    const float qw = 0.25f * (hi - lo);
                    const float m1 = lo + qw;
                    const float m2 = lo + 2.0f * qw;
                    const float m3 = lo + 3.0f * qw;
                    float s1 = 0.f, s2 = 0.f, s3 = 0.f;
                    #pragma unroll
                    for (int q = 0; q < 4; ++q) {
                        const float v = vq[q];
                        s1 += fminf(fmaxf(v - m1, -CMAX), CMAX);
                        s2 += fminf(fmaxf(v - m2, -CMAX), CMAX);
                        s3 += fminf(fmaxf(v - m3, -CMAX), CMAX);
                    }
                    #pragma unroll
                    for (int off = 16; off; off >>= 1) {
                        s1 += __shfl_xor_sync(0xffffffffu, s1, off);
                        s2 += __shfl_xor_sync(0xffffffffu, s2, off);
                        s3 += __shfl_xor_sync(0xffffffffu, s3, off);
                    }
                    float kf = 0.f;
                    if (s1 > 1.0f) kf += 1.0f;
                    if (s2 > 1.0f) kf += 1.0f;
                    if (s3 > 1.0f) kf += 1.0f;
                    lo = fmaf(kf, qw, lo);
                    hi = lo + qw;
                }
                tau = 0.5f * (lo + hi);
            }

            #pragma unroll
            for (int q = 0; q < 4; ++q)
                w_sh[lane + 32 * q] = fminf(fmaxf(vq[q] - tau, -CMAX), CMAX);

            BAR_ARRIVE(2);          // w is updated; release the others
        }
    }

    if (t < N_ASSETS) out[(size_t)b * N_ASSETS + t] = w_sh[t];
}

extern "C" void kernel_launch(void* const* d_in, const int* in_sizes, int n_in,
                              void* d_out, int out_size)
{
    const float* rets  = (const float*)d_in[0];   // [2048,128]
    const float* cov   = (const float*)d_in[1];   // [2048,128,128]
    const float* gamma = (const float*)d_in[2];   // [2048]
    const float* alpha = (const float*)d_in[3];   // [2048]
    float* out = (float*)d_out;                   // [2048,128]

    markowitz_kernel<<<BATCH, 256>>>(rets, cov, gamma, alpha, out);
}